// round 12
// baseline (speedup 1.0000x reference)
#include <cuda_runtime.h>

#define GAMMA_ 10.0f
#define EPS_   1e-6f

constexpr int Cn = 1000;  // classes
constexpr int Bn = 128;   // batch
constexpr int SPLITK = 2;
constexpr int NPROD = 32;

// ---------------- device scratch ----------------
__device__ float g_U[128 * 1024];          // gathered target columns W[:,t_i]
__device__ float g_npart[32][1024];        // column-norm partials (32-row slabs)
__device__ float g_norm[1024];             // reduced column norms
__device__ float g_P[SPLITK][256][1024];   // rows 0..127 logits, 128..255 gram
__device__ int   g_flag;                   // producer-done counter (reset by k3)

// ---------------- k2_fused: producers + tf32 GEMM + norm reduce, one launch ----
// blockIdx.y (mb): 0 = producers (gather + norm partials, 32 blocks)
//                  1,2 = logits GEMM (A rows, ungated)
//                  3,4 = gram GEMM (U rows, gated on producers)
//                  5 = norm reduce (gated) + zero out
constexpr int PA = 36;   // conflict-free A frag loads
constexpr int PB = 72;   // conflict-free B frag loads

__global__ __launch_bounds__(256) void k2_fused(const float* __restrict__ A,
                                                const float* __restrict__ W,
                                                const int* __restrict__ targets,
                                                float* __restrict__ out) {
    const int tid = threadIdx.x;
    const int mb = blockIdx.y;
    const int kb = blockIdx.z;

    if (mb == 0) {
        // ---- producer: 32 blocks, rc = x + 16*z owns a 32-row slab of W ----
        const int rc = blockIdx.x + 16 * kb;
        const int r0 = rc * 32;
        __shared__ int s_t[128];
        if (tid < 128) s_t[tid] = targets[tid];
        __syncthreads();

        for (int q = 0; q < 4; ++q) {
            const int c = q * 256 + tid;
            if (c < Cn) {
                float wreg[32];
                float acc = 0.0f;
#pragma unroll
                for (int j = 0; j < 32; ++j) {
                    float w = W[(size_t)(r0 + j) * Cn + c];
                    wreg[j] = w;
                    acc = fmaf(w, w, acc);
                }
                g_npart[rc][c] = acc;
#pragma unroll 4
                for (int j = 0; j < 128; ++j) {
                    if (s_t[j] == c) {
                        float* dst = g_U + (size_t)j * 1024 + r0;
#pragma unroll
                        for (int k = 0; k < 32; k += 4)
                            *(float4*)(dst + k) =
                                make_float4(wreg[k], wreg[k + 1], wreg[k + 2], wreg[k + 3]);
                    }
                }
            }
        }
        __threadfence();
        __syncthreads();
        if (tid == 0) atomicAdd(&g_flag, 1);
        return;
    }

    if (mb == 5) {
        if (kb == 0 && blockIdx.x == 8 && tid == 0) out[0] = 0.0f;
        if (kb == 0 && blockIdx.x < 8) {
            if (tid == 0) {
                volatile int* f = &g_flag;
                while (*f < NPROD) __nanosleep(128);
            }
            __syncthreads();
            __threadfence();
            const int c = blockIdx.x * 128 + tid;
            if (tid < 128) {
                float s = 0.0f;
#pragma unroll
                for (int p = 0; p < 32; ++p) s += g_npart[p][c];
                g_norm[c] = s;
            }
        }
        return;
    }

    // ---- GEMM lanes (128 active threads; upper half idles through barriers) ----
    __shared__ __align__(16) unsigned As[2][64][PA];
    __shared__ __align__(16) unsigned Bs[2][32][PB];

    const bool gram = (mb >= 3);
    if (gram) {
        if (tid == 0) {
            volatile int* f = &g_flag;
            while (*f < NPROD) __nanosleep(128);
        }
        __syncthreads();
        __threadfence();
    }

    const int n0 = blockIdx.x * 64;
    const float* Asrc = gram ? (g_U + (size_t)(mb - 3) * 64 * 1024)
                             : (A + (size_t)(mb - 1) * 64 * 1024);
    const int kbase = kb * 512;
    const bool worker = (tid < 128);
    const int lane = tid & 31, wid = tid >> 5;
    const int wm = wid & 1, wn = wid >> 1;

    float acc[2][4][4];
#pragma unroll
    for (int i = 0; i < 2; ++i)
#pragma unroll
        for (int j = 0; j < 4; ++j)
#pragma unroll
            for (int k = 0; k < 4; ++k) acc[i][j][k] = 0.f;

    uint4 pa[4], pb[4];
    auto ldchunk = [&](int kc) {
        const int k0 = kbase + kc * 32;
#pragma unroll
        for (int p = 0; p < 4; ++p) {
            int i = tid + 128 * p;
            int row = i >> 3, kq = i & 7;
            pa[p] = *(const uint4*)(Asrc + row * 1024 + k0 + kq * 4);
            int r = i >> 4, nq = i & 15;
            int gc = n0 + nq * 4;
            pb[p] = (gc < Cn) ? *(const uint4*)(W + (size_t)(k0 + r) * Cn + gc)
                              : make_uint4(0u, 0u, 0u, 0u);
        }
    };
    auto stchunk = [&](int bf) {
#pragma unroll
        for (int p = 0; p < 4; ++p) {
            int i = tid + 128 * p;
            int row = i >> 3, kq = i & 7;
            *(uint4*)&As[bf][row][kq * 4] = pa[p];
            int r = i >> 4, nq = i & 15;
            *(uint4*)&Bs[bf][r][nq * 4] = pb[p];
        }
    };

    if (worker) { ldchunk(0); stchunk(0); }
    __syncthreads();

    for (int ch = 0; ch < 16; ++ch) {
        if (worker) {
            if (ch < 15) ldchunk(ch + 1);
            const int bf = ch & 1;
            const int gid = lane >> 2, q = lane & 3;
#pragma unroll
            for (int ks = 0; ks < 4; ++ks) {
                const int col = ks * 8 + q;
                unsigned a[2][4], b[4][2];
#pragma unroll
                for (int mf = 0; mf < 2; ++mf) {
                    int r = wm * 32 + mf * 16 + gid;
                    a[mf][0] = As[bf][r][col];
                    a[mf][1] = As[bf][r + 8][col];
                    a[mf][2] = As[bf][r][col + 4];
                    a[mf][3] = As[bf][r + 8][col + 4];
                }
#pragma unroll
                for (int nf = 0; nf < 4; ++nf) {
                    int nn = wn * 32 + nf * 8 + gid;
                    b[nf][0] = Bs[bf][col][nn];
                    b[nf][1] = Bs[bf][col + 4][nn];
                }
#pragma unroll
                for (int mf = 0; mf < 2; ++mf)
#pragma unroll
                    for (int nf = 0; nf < 4; ++nf)
                        asm volatile(
                            "mma.sync.aligned.m16n8k8.row.col.f32.tf32.tf32.f32 "
                            "{%0,%1,%2,%3},{%4,%5,%6,%7},{%8,%9},{%0,%1,%2,%3};"
                            : "+f"(acc[mf][nf][0]), "+f"(acc[mf][nf][1]),
                              "+f"(acc[mf][nf][2]), "+f"(acc[mf][nf][3])
                            : "r"(a[mf][0]), "r"(a[mf][1]), "r"(a[mf][2]), "r"(a[mf][3]),
                              "r"(b[nf][0]), "r"(b[nf][1]));
            }
        }
        if (ch < 15) {
            __syncthreads();
            if (worker) stchunk((ch + 1) & 1);
            __syncthreads();
        }
    }

    if (worker) {
        const int m0 = gram ? ((mb - 3) * 64 + 128) : ((mb - 1) * 64);
        const int gid = lane >> 2, q = lane & 3;
#pragma unroll
        for (int mf = 0; mf < 2; ++mf) {
            int row = m0 + wm * 32 + mf * 16 + gid;
#pragma unroll
            for (int nf = 0; nf < 4; ++nf) {
                int coln = n0 + wn * 32 + nf * 8 + 2 * q;
                *(float2*)&g_P[kb][row][coln]     = make_float2(acc[mf][nf][0], acc[mf][nf][1]);
                *(float2*)&g_P[kb][row + 8][coln] = make_float2(acc[mf][nf][2], acc[mf][nf][3]);
            }
        }
    }
}

// ---------------- k3: per-row max violation (4 classes/thread), mean into out ----
__global__ __launch_bounds__(256) void k3_loss(const float* __restrict__ bvec,
                                               const int* __restrict__ targets,
                                               float* __restrict__ out) {
    const int i = blockIdx.x;
    const int tid = threadIdx.x;
    if (i == 0 && tid == 0) g_flag = 0;   // reset gate for the next replay
    const int t = targets[i];
    __shared__ float s_corr, s_nt;
    __shared__ float red[8];

    if (tid == 0) {
        s_corr = g_P[0][i][t] + g_P[1][i][t] + bvec[t];
        s_nt = g_norm[t];
    }
    __syncthreads();
    const float corr = s_corr, nt = s_nt;

    float vmax = 0.0f;
#pragma unroll
    for (int j = 0; j < 4; ++j) {
        const int c = tid + j * 256;
        if (c < Cn && c != t) {
            float lg = g_P[0][i][c] + g_P[1][i][c] + bvec[c];
            float gr = g_P[0][i + 128][c] + g_P[1][i + 128][c];
            float ss = g_norm[c] + nt - 2.0f * gr;
            float dn = sqrtf(ss + EPS_) + EPS_;
            float v = fmaxf(0.0f, GAMMA_ + (lg - corr) / dn);
            vmax = fmaxf(vmax, v);
        }
    }
#pragma unroll
    for (int o = 16; o; o >>= 1) vmax = fmaxf(vmax, __shfl_xor_sync(~0u, vmax, o));
    if ((tid & 31) == 0) red[tid >> 5] = vmax;
    __syncthreads();
    if (tid == 0) {
        float r = red[0];
#pragma unroll
        for (int w = 1; w < 8; ++w) r = fmaxf(r, red[w]);
        atomicAdd(out, r * (1.0f / 128.0f));
    }
}

// ---------------- launch ----------------
extern "C" void kernel_launch(void* const* d_in, const int* in_sizes, int n_in,
                              void* d_out, int out_size) {
    const float* A = (const float*)d_in[0];        // [128,1024]
    const float* W = (const float*)d_in[1];        // [1024,1000]
    const float* b = (const float*)d_in[2];        // [1000]
    const int* targets = (const int*)d_in[3];      // [128]
    float* out = (float*)d_out;

    k2_fused<<<dim3(16, 6, SPLITK), 256>>>(A, W, targets, out);
    k3_loss<<<Bn, 256>>>(b, targets, out);
}

// round 13
// speedup vs baseline: 2.3012x; 2.3012x over previous
#include <cuda_runtime.h>

#define GAMMA_ 10.0f
#define EPS_   1e-6f

constexpr int Cn = 1000;  // classes
constexpr int Bn = 128;   // batch
constexpr int SPLITK = 2;

// ---------------- device scratch ----------------
__device__ float g_U[128 * 1024];          // gathered target columns W[:,t_i]
__device__ float g_npart[64][1024];        // column-norm partials (16-row slabs)
__device__ float g_norm[1024];             // reduced column norms
__device__ float g_P[SPLITK][256][1024];   // rows 0..127 logits, 128..255 gram

// ---------------- k1: single-W-pass transpose-gather + fused norm partials ----------------
// 256 blocks: (kc = bid>>2) 16-row slab, (cc = bid&3) 250-column panel.
// Panel streamed through smem once: norm partial accumulated during load,
// then target columns written out coalesced (64B bursts).
__global__ __launch_bounds__(256) void k1_prep(const float* __restrict__ W,
                                               const int* __restrict__ targets) {
    __shared__ float srow[16][250];
    __shared__ int s_t[128];
    const int tid = threadIdx.x;
    const int k0 = (blockIdx.x >> 2) * 16;
    const int c0 = (blockIdx.x & 3) * 250;
    if (tid < 128) s_t[tid] = targets[tid];

    if (tid < 250) {
        float acc = 0.0f;
#pragma unroll
        for (int r = 0; r < 16; ++r) {
            float v = W[(size_t)(k0 + r) * Cn + c0 + tid];
            srow[r][tid] = v;
            acc = fmaf(v, v, acc);
        }
        g_npart[k0 >> 4][c0 + tid] = acc;
    }
    __syncthreads();

    const int lane = tid & 31, wid = tid >> 5;
    const int stream = wid * 2 + (lane >> 4);   // 0..15
    const int sub = lane & 15;                  // k offset within the 16-row slab
#pragma unroll
    for (int rep = 0; rep < 8; ++rep) {
        const int j = stream + rep * 16;        // sample index 0..127
        const int t = s_t[j];
        if (t >= c0 && t < c0 + 250)
            g_U[(size_t)j * 1024 + k0 + sub] = srow[sub][t - c0];
    }
}

// ---------------- k2: tf32 mma.sync GEMM, CTA 64x64, 4 warps, split-K=2 ----
// blockIdx.y (mb): 0,1 = A row-halves; 2,3 = U row-halves; 4 = norm reduce + zero out
constexpr int PA = 36;   // conflict-free A frag loads
constexpr int PB = 72;   // conflict-free B frag loads

__global__ __launch_bounds__(128) void k2_gemm(const float* __restrict__ A,
                                               const float* __restrict__ W,
                                               float* __restrict__ out) {
    const int tid = threadIdx.x;
    const int mb = blockIdx.y;
    const int kb = blockIdx.z;

    if (mb == 4) {
        if (kb == 0) {
            if (blockIdx.x < 8) {
                const int c = blockIdx.x * 128 + tid;
                float s = 0.0f;
#pragma unroll
                for (int p = 0; p < 64; ++p) s += g_npart[p][c];
                g_norm[c] = s;
            } else if (blockIdx.x == 8 && tid == 0) {
                out[0] = 0.0f;
            }
        }
        return;
    }

    __shared__ __align__(16) unsigned As[2][64][PA];
    __shared__ __align__(16) unsigned Bs[2][32][PB];

    const int lane = tid & 31, wid = tid >> 5;
    const int wm = wid & 1, wn = wid >> 1;
    const int n0 = blockIdx.x * 64;
    const float* Asrc = (mb < 2) ? (A + (size_t)mb * 64 * 1024)
                                 : (g_U + (size_t)(mb - 2) * 64 * 1024);
    const int kbase = kb * 512;

    float acc[2][4][4];
#pragma unroll
    for (int i = 0; i < 2; ++i)
#pragma unroll
        for (int j = 0; j < 4; ++j)
#pragma unroll
            for (int k = 0; k < 4; ++k) acc[i][j][k] = 0.f;

    uint4 pa[4], pb[4];
    auto ldchunk = [&](int kc) {
        const int k0 = kbase + kc * 32;
#pragma unroll
        for (int p = 0; p < 4; ++p) {
            int i = tid + 128 * p;
            int row = i >> 3, kq = i & 7;
            pa[p] = *(const uint4*)(Asrc + row * 1024 + k0 + kq * 4);
            int r = i >> 4, nq = i & 15;
            int gc = n0 + nq * 4;
            pb[p] = (gc < Cn) ? *(const uint4*)(W + (size_t)(k0 + r) * Cn + gc)
                              : make_uint4(0u, 0u, 0u, 0u);
        }
    };
    auto stchunk = [&](int bf) {
#pragma unroll
        for (int p = 0; p < 4; ++p) {
            int i = tid + 128 * p;
            int row = i >> 3, kq = i & 7;
            *(uint4*)&As[bf][row][kq * 4] = pa[p];
            int r = i >> 4, nq = i & 15;
            *(uint4*)&Bs[bf][r][nq * 4] = pb[p];
        }
    };

    ldchunk(0);
    stchunk(0);
    __syncthreads();

    for (int ch = 0; ch < 16; ++ch) {
        if (ch < 15) ldchunk(ch + 1);
        const int bf = ch & 1;
        const int gid = lane >> 2, q = lane & 3;
#pragma unroll
        for (int ks = 0; ks < 4; ++ks) {
            const int col = ks * 8 + q;
            unsigned a[2][4], b[4][2];
#pragma unroll
            for (int mf = 0; mf < 2; ++mf) {
                int r = wm * 32 + mf * 16 + gid;
                a[mf][0] = As[bf][r][col];
                a[mf][1] = As[bf][r + 8][col];
                a[mf][2] = As[bf][r][col + 4];
                a[mf][3] = As[bf][r + 8][col + 4];
            }
#pragma unroll
            for (int nf = 0; nf < 4; ++nf) {
                int nn = wn * 32 + nf * 8 + gid;
                b[nf][0] = Bs[bf][col][nn];
                b[nf][1] = Bs[bf][col + 4][nn];
            }
#pragma unroll
            for (int mf = 0; mf < 2; ++mf)
#pragma unroll
                for (int nf = 0; nf < 4; ++nf)
                    asm volatile(
                        "mma.sync.aligned.m16n8k8.row.col.f32.tf32.tf32.f32 "
                        "{%0,%1,%2,%3},{%4,%5,%6,%7},{%8,%9},{%0,%1,%2,%3};"
                        : "+f"(acc[mf][nf][0]), "+f"(acc[mf][nf][1]),
                          "+f"(acc[mf][nf][2]), "+f"(acc[mf][nf][3])
                        : "r"(a[mf][0]), "r"(a[mf][1]), "r"(a[mf][2]), "r"(a[mf][3]),
                          "r"(b[nf][0]), "r"(b[nf][1]));
        }
        if (ch < 15) {
            __syncthreads();
            stchunk((ch + 1) & 1);
            __syncthreads();
        }
    }

    const int m0 = mb * 64, gid = lane >> 2, q = lane & 3;
#pragma unroll
    for (int mf = 0; mf < 2; ++mf) {
        int row = m0 + wm * 32 + mf * 16 + gid;
#pragma unroll
        for (int nf = 0; nf < 4; ++nf) {
            int coln = n0 + wn * 32 + nf * 8 + 2 * q;
            *(float2*)&g_P[kb][row][coln]     = make_float2(acc[mf][nf][0], acc[mf][nf][1]);
            *(float2*)&g_P[kb][row + 8][coln] = make_float2(acc[mf][nf][2], acc[mf][nf][3]);
        }
    }
}

// ---------------- k3: per-row max violation (4 consecutive classes/thread, float4) ----
__global__ __launch_bounds__(256) void k3_loss(const float* __restrict__ bvec,
                                               const int* __restrict__ targets,
                                               float* __restrict__ out) {
    const int i = blockIdx.x;
    const int tid = threadIdx.x;
    const int t = targets[i];
    __shared__ float s_corr, s_nt;
    __shared__ float red[8];

    if (tid == 0) {
        s_corr = g_P[0][i][t] + g_P[1][i][t] + bvec[t];
        s_nt = g_norm[t];
    }
    __syncthreads();
    const float corr = s_corr, nt = s_nt;

    float vmax = 0.0f;
    if (tid < 250) {
        const int c4 = tid * 4;
        float4 p0 = *(const float4*)&g_P[0][i][c4];
        float4 p1 = *(const float4*)&g_P[1][i][c4];
        float4 q0 = *(const float4*)&g_P[0][i + 128][c4];
        float4 q1 = *(const float4*)&g_P[1][i + 128][c4];
        float4 nr = *(const float4*)&g_norm[c4];
        float4 bb = *(const float4*)&bvec[c4];

        float lg[4] = {p0.x + p1.x + bb.x, p0.y + p1.y + bb.y,
                       p0.z + p1.z + bb.z, p0.w + p1.w + bb.w};
        float gr[4] = {q0.x + q1.x, q0.y + q1.y, q0.z + q1.z, q0.w + q1.w};
        float nc[4] = {nr.x, nr.y, nr.z, nr.w};
#pragma unroll
        for (int j = 0; j < 4; ++j) {
            const int c = c4 + j;
            float ss = nc[j] + nt - 2.0f * gr[j];
            float dn = sqrtf(ss + EPS_) + EPS_;
            float v = fmaxf(0.0f, GAMMA_ + (lg[j] - corr) / dn);
            if (c != t) vmax = fmaxf(vmax, v);
        }
    }
#pragma unroll
    for (int o = 16; o; o >>= 1) vmax = fmaxf(vmax, __shfl_xor_sync(~0u, vmax, o));
    if ((tid & 31) == 0) red[tid >> 5] = vmax;
    __syncthreads();
    if (tid == 0) {
        float r = red[0];
#pragma unroll
        for (int w = 1; w < 8; ++w) r = fmaxf(r, red[w]);
        atomicAdd(out, r * (1.0f / 128.0f));
    }
}

// ---------------- launch ----------------
extern "C" void kernel_launch(void* const* d_in, const int* in_sizes, int n_in,
                              void* d_out, int out_size) {
    const float* A = (const float*)d_in[0];        // [128,1024]
    const float* W = (const float*)d_in[1];        // [1024,1000]
    const float* b = (const float*)d_in[2];        // [1000]
    const int* targets = (const int*)d_in[3];      // [128]
    float* out = (float*)d_out;

    k1_prep<<<256, 256>>>(W, targets);
    k2_gemm<<<dim3(16, 5, SPLITK), 128>>>(A, W, out);
    k3_loss<<<Bn, 256>>>(b, targets, out);
}